// round 16
// baseline (speedup 1.0000x reference)
#include <cuda_runtime.h>

#define N 4096
#define B 8
#define JT 128             // threads per block
#define ICH 64             // i per chunk
#define NCHUNK (N / ICH)   // 64
#define NJT (N / JT)       // 32

#define EXP_NEG1 0.36787944117144233f
#define DVAL 2.3504023872876028f
#define INV_D2 (1.0f / (DVAL * DVAL))
#define EPS 1e-5f

typedef unsigned long long ull;

// -------- packed f32x2 helpers --------
__device__ __forceinline__ ull pk(float lo, float hi) {
    ull r; asm("mov.b64 %0, {%1, %2};" : "=l"(r) : "f"(lo), "f"(hi)); return r;
}
__device__ __forceinline__ void upk(ull v, float& lo, float& hi) {
    asm("mov.b64 {%0, %1}, %2;" : "=f"(lo), "=f"(hi) : "l"(v));
}
__device__ __forceinline__ ull padd(ull a, ull b) {
    ull r; asm("add.rn.f32x2 %0, %1, %2;" : "=l"(r) : "l"(a), "l"(b)); return r;
}
__device__ __forceinline__ ull pmul(ull a, ull b) {
    ull r; asm("mul.rn.f32x2 %0, %1, %2;" : "=l"(r) : "l"(a), "l"(b)); return r;
}
__device__ __forceinline__ ull pfma(ull a, ull b, ull c) {
    ull r; asm("fma.rn.f32x2 %0, %1, %2, %3;" : "=l"(r) : "l"(a), "l"(b), "l"(c)); return r;
}
__device__ __forceinline__ float rsqrt_ap(float v) {
    float r; asm("rsqrt.approx.f32 %0, %1;" : "=f"(r) : "f"(v)); return r;
}

// -------- device scratch (no allocations allowed) --------
__device__ float4 g_part[NCHUNK][N][2];   // partial sums [chunk][j] -> 8 floats
__device__ int g_cnt[NJT];                // arrival counters (zero-init)

// One i-pair stream: geometry + packed poly-exp gate + pair-packed accumulate.
// P(v) = e^v - e^{-1} via degree-8 Taylor (|v| <= 1), constant term folded.
__device__ __forceinline__ void stream_body(
    const ulonglong2 q0, const ulonglong2 q1, const ulonglong2 q2,
    const ulonglong2 x01, const ulonglong2 x23,
    const ulonglong2 x45, const ulonglong2 x67,
    const ull pjx2, const ull pjy2, const ull pjz2,
    const ull inx2, const ull iny2, const ull inz2,
    const ull C0, const ull C1, const ull C2, const ull C3, const ull C4,
    const ull C5, const ull C6, const ull C7, const ull C8,
    ull& a0, ull& a1, ull& a2, ull& a3,
    ull& a4, ull& a5, ull& a6, ull& a7)
{
    ull dx = padd(pjx2, q0.x);
    ull dy = padd(pjy2, q0.y);
    ull dz = padd(pjz2, q1.x);

    ull d2 = pfma(dx, dx, pfma(dy, dy, pmul(dz, dz)));
    ull da = pfma(dx, q1.y, pfma(dy, q2.x, pmul(dz, q2.y)));   // delta . outdir_i
    ull db = pfma(dx, inx2, pfma(dy, iny2, pmul(dz, inz2)));   // delta . indir_j

    float d20, d21; upk(d2, d20, d21);
    ull rp = pk(rsqrt_ap(fmaxf(d20, EPS)), rsqrt_ap(fmaxf(d21, EPS)));

    ull va = pmul(da, rp);   // in [-1, 1]
    ull vb = pmul(db, rp);   // in [-1, 1]

    ull Ea = pfma(va, C8, C7);
    Ea = pfma(va, Ea, C6); Ea = pfma(va, Ea, C5); Ea = pfma(va, Ea, C4);
    Ea = pfma(va, Ea, C3); Ea = pfma(va, Ea, C2); Ea = pfma(va, Ea, C1);
    Ea = pfma(va, Ea, C0);
    ull Eb = pfma(vb, C8, C7);
    Eb = pfma(vb, Eb, C6); Eb = pfma(vb, Eb, C5); Eb = pfma(vb, Eb, C4);
    Eb = pfma(vb, Eb, C3); Eb = pfma(vb, Eb, C2); Eb = pfma(vb, Eb, C1);
    Eb = pfma(vb, Eb, C0);

    ull g = pmul(Ea, Eb);    // packed {gate_i0, gate_i1} — used directly

    a0 = pfma(x01.x, g, a0);
    a1 = pfma(x01.y, g, a1);
    a2 = pfma(x23.x, g, a2);
    a3 = pfma(x23.y, g, a3);
    a4 = pfma(x45.x, g, a4);
    a5 = pfma(x45.y, g, a5);
    a6 = pfma(x67.x, g, a6);
    a7 = pfma(x67.y, g, a7);
}

// -------- single fused kernel --------
__global__ void __launch_bounds__(JT, 4) fused_kernel(const float* __restrict__ x,
                                                      const float* __restrict__ pos,
                                                      const float* __restrict__ indir,
                                                      const float* __restrict__ outdir,
                                                      const float* __restrict__ power,
                                                      const float* __restrict__ bias,
                                                      float* __restrict__ out) {
    // i-side geometry, pair-SoA per pair p (i=2p,2p+1):
    // [-px0,-px1, -py0,-py1, -pz0,-pz1, ox0,ox1, oy0,oy1, oz0,oz1]
    __shared__ float sG[(ICH / 2) * 12];             // 1.5 KB
    // x pair-interleaved: sXpf[(p*8+b)*2 + h] = x[b][2p+h]  (2 KB)
    __shared__ float sXpf[(ICH / 2) * 8 * 2];
    __shared__ int s_last;

    const int tid   = threadIdx.x;
    const int jtile = blockIdx.x;
    const int chunk = blockIdx.y;
    const int i0    = chunk * ICH;
    const int j     = jtile * JT + tid;

    // ---- stage i-chunk (threads 0..63 own one i each for geometry) ----
    if (tid < ICH) {
        const int i = i0 + tid;
        const int p = tid >> 1, h = tid & 1;
        float* gp_ = sG + p * 12;
        gp_[0  + h] = -pos[3 * i + 0];
        gp_[2  + h] = -pos[3 * i + 1];
        gp_[4  + h] = -pos[3 * i + 2];
        gp_[6  + h] = outdir[3 * i + 0];
        gp_[8  + h] = outdir[3 * i + 1];
        gp_[10 + h] = outdir[3 * i + 2];
    }
    {
        // x stage: threads 0-63 do b=0..3, threads 64-127 do b=4..7
        const int ii = tid & (ICH - 1);
        const int p = ii >> 1, h = ii & 1;
        const int b0 = (tid >> 6) * 4;
        #pragma unroll
        for (int b = b0; b < b0 + 4; b++)
            sXpf[(p * 8 + b) * 2 + h] = x[b * N + i0 + ii];
    }

    // ---- j-side registers (packed broadcasts) ----
    const ull pjx2 = pk(pos[3 * j + 0], pos[3 * j + 0]);
    const ull pjy2 = pk(pos[3 * j + 1], pos[3 * j + 1]);
    const ull pjz2 = pk(pos[3 * j + 2], pos[3 * j + 2]);
    const float inx = indir[3 * j + 0];
    const float iny = indir[3 * j + 1];
    const float inz = indir[3 * j + 2];
    const ull inx2 = pk(inx, inx), iny2 = pk(iny, iny), inz2 = pk(inz, inz);

    // poly coefficients: e^v Taylor deg-8, constant term folded with -e^{-1}
    const ull C0 = pk(1.0f - EXP_NEG1, 1.0f - EXP_NEG1);
    const ull C1 = pk(1.0f, 1.0f);
    const ull C2 = pk(0.5f, 0.5f);
    const ull C3 = pk(1.0f / 6.0f, 1.0f / 6.0f);
    const ull C4 = pk(1.0f / 24.0f, 1.0f / 24.0f);
    const ull C5 = pk(1.0f / 120.0f, 1.0f / 120.0f);
    const ull C6 = pk(1.0f / 720.0f, 1.0f / 720.0f);
    const ull C7 = pk(1.0f / 5040.0f, 1.0f / 5040.0f);
    const ull C8 = pk(1.0f / 40320.0f, 1.0f / 40320.0f);

    __syncthreads();

    // 8 pair-packed accumulators: acc_b = { sum over even i, sum over odd i }
    ull a0 = 0ull, a1 = 0ull, a2 = 0ull, a3 = 0ull;
    ull a4 = 0ull, a5 = 0ull, a6 = 0ull, a7 = 0ull;

    #pragma unroll 2
    for (int p = 0; p < ICH / 2; p += 2) {
        const ulonglong2* gqA = reinterpret_cast<const ulonglong2*>(sG + p * 12);
        const ulonglong2* gqB = reinterpret_cast<const ulonglong2*>(sG + (p + 1) * 12);
        ulonglong2 qA0 = gqA[0], qA1 = gqA[1], qA2 = gqA[2];
        ulonglong2 qB0 = gqB[0], qB1 = gqB[1], qB2 = gqB[2];

        const ulonglong2* XA = reinterpret_cast<const ulonglong2*>(sXpf + p * 16);
        ulonglong2 xA01 = XA[0], xA23 = XA[1], xA45 = XA[2], xA67 = XA[3];
        ulonglong2 xB01 = XA[4], xB23 = XA[5], xB45 = XA[6], xB67 = XA[7];

        stream_body(qA0, qA1, qA2, xA01, xA23, xA45, xA67,
                    pjx2, pjy2, pjz2, inx2, iny2, inz2,
                    C0, C1, C2, C3, C4, C5, C6, C7, C8,
                    a0, a1, a2, a3, a4, a5, a6, a7);
        stream_body(qB0, qB1, qB2, xB01, xB23, xB45, xB67,
                    pjx2, pjy2, pjz2, inx2, iny2, inz2,
                    C0, C1, C2, C3, C4, C5, C6, C7, C8,
                    a0, a1, a2, a3, a4, a5, a6, a7);
    }

    // ---- collapse pair-packed accumulators and write partials ----
    {
        float lo, hi;
        float s[8];
        upk(a0, lo, hi); s[0] = lo + hi;
        upk(a1, lo, hi); s[1] = lo + hi;
        upk(a2, lo, hi); s[2] = lo + hi;
        upk(a3, lo, hi); s[3] = lo + hi;
        upk(a4, lo, hi); s[4] = lo + hi;
        upk(a5, lo, hi); s[5] = lo + hi;
        upk(a6, lo, hi); s[6] = lo + hi;
        upk(a7, lo, hi); s[7] = lo + hi;
        float4* pp = &g_part[chunk][j][0];
        pp[0] = make_float4(s[0], s[1], s[2], s[3]);
        pp[1] = make_float4(s[4], s[5], s[6], s[7]);
    }

    // ---- last-block-per-column reduction + epilogue ----
    __threadfence();
    __syncthreads();
    if (tid == 0)
        s_last = (atomicAdd(&g_cnt[jtile], 1) == NCHUNK - 1);
    __syncthreads();

    if (s_last) {
        float s0 = 0.f, s1 = 0.f, s2 = 0.f, s3 = 0.f;
        float s4 = 0.f, s5 = 0.f, s6 = 0.f, s7 = 0.f;
        #pragma unroll 8
        for (int c = 0; c < NCHUNK; c++) {
            float4 a = __ldcg(&g_part[c][j][0]);
            float4 b = __ldcg(&g_part[c][j][1]);
            s0 += a.x; s1 += a.y; s2 += a.z; s3 += a.w;
            s4 += b.x; s5 += b.y; s6 += b.z; s7 += b.w;
        }
        float pw = power[j] * INV_D2;
        float bi = bias[j];
        float v;
        v = fmaf(s0, pw, -bi); out[0 * N + j] = v > 0.f ? v : expm1f(v);
        v = fmaf(s1, pw, -bi); out[1 * N + j] = v > 0.f ? v : expm1f(v);
        v = fmaf(s2, pw, -bi); out[2 * N + j] = v > 0.f ? v : expm1f(v);
        v = fmaf(s3, pw, -bi); out[3 * N + j] = v > 0.f ? v : expm1f(v);
        v = fmaf(s4, pw, -bi); out[4 * N + j] = v > 0.f ? v : expm1f(v);
        v = fmaf(s5, pw, -bi); out[5 * N + j] = v > 0.f ? v : expm1f(v);
        v = fmaf(s6, pw, -bi); out[6 * N + j] = v > 0.f ? v : expm1f(v);
        v = fmaf(s7, pw, -bi); out[7 * N + j] = v > 0.f ? v : expm1f(v);
        if (tid == 0) g_cnt[jtile] = 0;   // reset for next graph replay
    }
}

extern "C" void kernel_launch(void* const* d_in, const int* in_sizes, int n_in,
                              void* d_out, int out_size) {
    const float* x      = (const float*)d_in[0];
    const float* pos    = (const float*)d_in[1];
    const float* indir  = (const float*)d_in[2];
    const float* outdir = (const float*)d_in[3];
    const float* power  = (const float*)d_in[4];
    const float* bias   = (const float*)d_in[5];
    float* out = (float*)d_out;

    dim3 grid(NJT, NCHUNK);
    fused_kernel<<<grid, JT>>>(x, pos, indir, outdir, power, bias, out);
}